// round 7
// baseline (speedup 1.0000x reference)
#include <cuda_runtime.h>
#include <math.h>

#define BATCH 64
#define TSTEPS 1024
#define IND 64
#define HD 512
#define OUTD 64
#define NCTA 128
#define NTHR 512

typedef unsigned long long ull;

// ---------------- persistent device state ----------------
__device__ __align__(16) float g_h1[2][HD * BATCH];        // [j][b], b contiguous
__device__ __align__(16) float g_h2[2][HD * BATCH];
__device__ __align__(16) float g_xT[TSTEPS * IND * BATCH]; // [t][k][b]
__device__ unsigned g_gen;
__device__ unsigned g_count;

// ---------------- grid-wide sense barrier (128 CTAs, 1/SM) ----------------
__device__ __forceinline__ void grid_barrier() {
    __syncthreads();
    if (threadIdx.x == 0) {
        __threadfence();
        volatile unsigned* vg = &g_gen;
        unsigned my = *vg;
        if (atomicAdd(&g_count, 1u) == NCTA - 1u) {
            g_count = 0u;
            __threadfence();
            *vg = my + 1u;
        } else {
            while (*vg == my) { }
        }
        __threadfence();
    }
    __syncthreads();
}

__device__ __forceinline__ float sigf(float x) { return 1.0f / (1.0f + __expf(-x)); }

// ---------------- packed f32x2 helpers ----------------
__device__ __forceinline__ ull splat2(float v) {
    ull r; asm("mov.b64 %0, {%1, %1};" : "=l"(r) : "f"(v)); return r;
}
__device__ __forceinline__ ull pack2(float lo, float hi) {
    ull r; asm("mov.b64 %0, {%1, %2};" : "=l"(r) : "f"(lo), "f"(hi)); return r;
}
__device__ __forceinline__ void ffma2(ull& d, ull a, ull b) {
    asm("fma.rn.f32x2 %0, %1, %2, %0;" : "+l"(d) : "l"(a), "l"(b));
}
__device__ __forceinline__ ull addf2(ull a, ull b) {
    ull r; asm("add.rn.f32x2 %0, %1, %2;" : "=l"(r) : "l"(a), "l"(b)); return r;
}
__device__ __forceinline__ void unpack2(ull v, float& lo, float& hi) {
    asm("mov.b64 {%0, %1}, %2;" : "=f"(lo), "=f"(hi) : "l"(v));
}

// ---------------- SMEM layout (byte offsets) ----------------
#define O_WA   0                 // 576 k * 16 ull (splatted [k][jj][type])
#define O_WB   73728             // 1024 k * 16 ull
#define O_RED  204800            // 8 rows * 128 ulonglong2 = 16384 B
#define O_BA   221184            // 16 ull
#define O_BB   221312
#define O_WO   221440            // 512 f
#define O_BO   223488
#define O_RY   223504            // 8*64 f
#define SMEM_BYTES 225552

// ---------------- MAC pipeline: blocks of 4 k, double buffered ----------------
__device__ __forceinline__ void ldblk(ulonglong2 (&hb)[4], const float* __restrict__ hsrc,
                                      int k, int boff) {
#pragma unroll
    for (int i = 0; i < 4; ++i)
        hb[i] = __ldcg((const ulonglong2*)(hsrc + (k + i) * 64 + boff));
}
__device__ __forceinline__ void mmblk(const ull* __restrict__ wp, const ulonglong2 (&hb)[4],
                                      ull (&acc)[2][4]) {
#pragma unroll
    for (int i = 0; i < 4; ++i) {
        const ulonglong2* w = (const ulonglong2*)(wp + i * 16);
        ulonglong2 wif = w[0], wgo = w[1];
        ffma2(acc[0][0], wif.x, hb[i].x); ffma2(acc[0][1], wif.y, hb[i].x);
        ffma2(acc[0][2], wgo.x, hb[i].x); ffma2(acc[0][3], wgo.y, hb[i].x);
        ffma2(acc[1][0], wif.x, hb[i].y); ffma2(acc[1][1], wif.y, hb[i].y);
        ffma2(acc[1][2], wgo.x, hb[i].y); ffma2(acc[1][3], wgo.y, hb[i].y);
    }
}
// n must be a multiple of 8 (64, 8, 72, 128 all are... 8 handled: one loop iter)
__device__ __forceinline__ void mac_run(const ull* __restrict__ wbase,
                                        const float* __restrict__ hsrc,
                                        int n, int boff, ull (&acc)[2][4]) {
    ulonglong2 hA[4], hB[4];
    ldblk(hA, hsrc, 0, boff);
    for (int k = 0; k + 8 <= n; k += 8) {
        ldblk(hB, hsrc, k + 4, boff);
        mmblk(wbase + k * 16, hA, acc);
        if (k + 8 < n) ldblk(hA, hsrc, k + 8, boff);
        mmblk(wbase + (k + 4) * 16, hB, acc);
    }
}

// ---------------- 3-round tree reduction (two independent halves) ------------
__device__ __forceinline__ void red_store(ulonglong2* row0, int slot, const ull (&acc)[2][4]) {
    row0[0 * 128 + slot] = make_ulonglong2(acc[0][0], acc[0][1]);
    row0[1 * 128 + slot] = make_ulonglong2(acc[0][2], acc[0][3]);
    row0[2 * 128 + slot] = make_ulonglong2(acc[1][0], acc[1][1]);
    row0[3 * 128 + slot] = make_ulonglong2(acc[1][2], acc[1][3]);
}
__device__ __forceinline__ void red_add(const ulonglong2* row0, int slot, ull (&acc)[2][4]) {
    ulonglong2 a0 = row0[0 * 128 + slot], a1 = row0[1 * 128 + slot];
    ulonglong2 a2 = row0[2 * 128 + slot], a3 = row0[3 * 128 + slot];
    acc[0][0] = addf2(acc[0][0], a0.x); acc[0][1] = addf2(acc[0][1], a0.y);
    acc[0][2] = addf2(acc[0][2], a1.x); acc[0][3] = addf2(acc[0][3], a1.y);
    acc[1][0] = addf2(acc[1][0], a2.x); acc[1][1] = addf2(acc[1][1], a2.y);
    acc[1][2] = addf2(acc[1][2], a3.x); acc[1][3] = addf2(acc[1][3], a3.y);
}
__device__ __forceinline__ void reduce_acc(ull (&acc)[2][4], ulonglong2* sRed,
                                           int kslc, int half, int lane) {
    ulonglong2* hr = sRed + half * (4 * 128);
    if (kslc >= 4) red_store(hr, (kslc - 4) * 32 + lane, acc);
    __syncthreads();
    if (kslc < 4) red_add(hr, kslc * 32 + lane, acc);
    __syncthreads();
    if (kslc >= 1 && kslc < 4) red_store(hr, (kslc - 1) * 32 + lane, acc);
    __syncthreads();
    if (kslc == 0) {
#pragma unroll
        for (int w = 0; w < 3; ++w) red_add(hr, w * 32 + lane, acc);
    }
}

// ---------------- activations + cell + h store (kslc==0 warps) ----------------
__device__ __forceinline__ void cell_update(ull (&acc)[2][4], ull (&cc)[2],
                                            float* __restrict__ hdst,
                                            int j0, int jj, int boff) {
    ull hout[2];
#pragma unroll
    for (int bp = 0; bp < 2; ++bp) {
        float gi0, gi1, gf0, gf1, gg0, gg1, go0, go1, c0, c1;
        unpack2(acc[bp][0], gi0, gi1);
        unpack2(acc[bp][1], gf0, gf1);
        unpack2(acc[bp][2], gg0, gg1);
        unpack2(acc[bp][3], go0, go1);
        unpack2(cc[bp], c0, c1);
        c0 = sigf(gf0) * c0 + sigf(gi0) * tanhf(gg0);
        c1 = sigf(gf1) * c1 + sigf(gi1) * tanhf(gg1);
        cc[bp] = pack2(c0, c1);
        hout[bp] = pack2(sigf(go0) * tanhf(c0), sigf(go1) * tanhf(c1));
    }
    *(ulonglong2*)(hdst + (j0 + jj) * 64 + boff) = make_ulonglong2(hout[0], hout[1]);
}

// ---------------- y(t) head: CTA c (<64) -> column c; 8-way k split ----------
__device__ __forceinline__ void do_y(int t, const float* __restrict__ h2v,
                                     int c, int tid,
                                     const float* sWO, const float* sBO,
                                     float* sRY, float* __restrict__ out) {
    int b = tid & 63, u = tid >> 6;   // u in 0..7
    if (c < OUTD) {
        float p = 0.0f;
        int k0 = u * 64;
#pragma unroll 8
        for (int k = 0; k < 64; ++k)
            p += __ldcg(h2v + (k0 + k) * 64 + b) * sWO[k0 + k];
        sRY[u * 64 + b] = p;
    }
    __syncthreads();
    if (c < OUTD && u == 0) {
        float y = sBO[0];
#pragma unroll
        for (int m = 0; m < 8; ++m) y += sRY[m * 64 + b];
        out[b * (TSTEPS * OUTD) + t * OUTD + c] = y;
    }
}

extern __shared__ char smem[];

__global__ void __launch_bounds__(NTHR, 1)
lstm_persistent_kernel(const float* __restrict__ x,
                       const float* __restrict__ Wih1, const float* __restrict__ Whh1,
                       const float* __restrict__ bih1, const float* __restrict__ bhh1,
                       const float* __restrict__ Wih2, const float* __restrict__ Whh2,
                       const float* __restrict__ bih2, const float* __restrict__ bhh2,
                       const float* __restrict__ Wout, const float* __restrict__ bout,
                       float* __restrict__ out) {
    ull* sWA = (ull*)(smem + O_WA);
    ull* sWB = (ull*)(smem + O_WB);
    ulonglong2* sRed = (ulonglong2*)(smem + O_RED);
    ull* sBA = (ull*)(smem + O_BA);
    ull* sBB = (ull*)(smem + O_BB);
    float* sWO = (float*)(smem + O_WO);
    float* sBO = (float*)(smem + O_BO);
    float* sRY = (float*)(smem + O_RY);

    const int tid  = threadIdx.x;
    const int c    = blockIdx.x;          // CTA owns j = c*4 .. c*4+3
    const int j0   = c * 4;
    const int warp = tid >> 5;
    const int lane = tid & 31;
    const int kslc = warp >> 1;           // k slice 0..7
    const int half = warp & 1;            // batch half 0..1
    const int jj   = lane & 3;
    const int bgrp = lane >> 2;           // 0..7
    const int boff = half * 32 + bgrp * 4;  // float offset in 64-wide b row

    // ---- stage splatted weights into SMEM (once) ----
    for (int i = tid; i < 576 * 16; i += NTHR) {
        int k = i >> 4, r = i & 15, jw = r >> 2, tp = r & 3;
        int row = tp * HD + j0 + jw;
        float v = (k < IND) ? Wih1[row * IND + k] : Whh1[row * HD + (k - IND)];
        sWA[i] = splat2(v);
    }
    for (int i = tid; i < 1024 * 16; i += NTHR) {
        int k = i >> 4, r = i & 15, jw = r >> 2, tp = r & 3;
        int row = tp * HD + j0 + jw;
        float v = (k < HD) ? Wih2[row * HD + k] : Whh2[row * HD + (k - HD)];
        sWB[i] = splat2(v);
    }
    if (tid < 16) {
        int jw = tid >> 2, tp = tid & 3;
        int row = tp * HD + j0 + jw;
        sBA[jw * 4 + tp] = splat2(bih1[row] + bhh1[row]);
        sBB[jw * 4 + tp] = splat2(bih2[row] + bhh2[row]);
    }
    if (c < OUTD) {
        for (int i = tid; i < HD; i += NTHR) sWO[i] = Wout[c * HD + i];
        if (tid == 0) sBO[0] = bout[c];
    }

    // ---- prologue: x -> [t][k][b]; zero h buffers ----
    for (int t = c * (TSTEPS / NCTA); t < (c + 1) * (TSTEPS / NCTA); ++t) {
        for (int i = tid; i < BATCH * IND; i += NTHR) {
            int b = i & 63, k = i >> 6;
            g_xT[t * (IND * BATCH) + k * 64 + b] = x[b * (TSTEPS * IND) + t * IND + k];
        }
    }
    if (c < 64) {
        int gi = c * NTHR + tid;
        g_h1[0][gi] = 0.0f; g_h1[1][gi] = 0.0f;
        g_h2[0][gi] = 0.0f; g_h2[1][gi] = 0.0f;
    }
    grid_barrier();

    ull cc1[2] = {0, 0}, cc2[2] = {0, 0};
    const ull* wA = sWA + jj * 4;
    const ull* wB = sWB + jj * 4;

    for (int t = 0; t < TSTEPS; ++t) {
        const int rp = t & 1, wb2 = rp ^ 1;
        const float* h1r = g_h1[rp];
        const float* h2r = g_h2[rp];
        const float* h1w = g_h1[wb2];

        // ======== phase A: gates1 = x_t W_ih1^T + h1 W_hh1^T + b ========
        ull acc[2][4];
#pragma unroll
        for (int i = 0; i < 2; ++i)
#pragma unroll
            for (int p = 0; p < 4; ++p)
                acc[i][p] = (kslc == 0) ? sBA[jj * 4 + p] : 0ull;

        if (kslc == 0) {
            mac_run(wA, g_xT + t * (IND * BATCH), 64, boff, acc);
            mac_run(wA + 64 * 16, h1r, 8, boff, acc);
        } else {
            mac_run(wA + (72 * kslc) * 16, h1r + (72 * kslc - 64) * 64, 72, boff, acc);
        }
        reduce_acc(acc, sRed, kslc, half, lane);
        if (kslc == 0) cell_update(acc, cc1, g_h1[wb2], j0, jj, boff);

        grid_barrier();   // publish h1(t); the ONLY grid barrier per step

        // deferred y(t-1) from h2(t-1)
        if (t > 0) do_y(t - 1, h2r, c, tid, sWO, sBO, sRY, out);

        // ======== phase B: gates2 = h1(t) W_ih2^T + h2(t-1) W_hh2^T + b ========
#pragma unroll
        for (int i = 0; i < 2; ++i)
#pragma unroll
            for (int p = 0; p < 4; ++p)
                acc[i][p] = (kslc == 0) ? sBB[jj * 4 + p] : 0ull;

        if (kslc < 4) {
            mac_run(wB + (128 * kslc) * 16, h1w + (128 * kslc) * 64, 128, boff, acc);
        } else {
            mac_run(wB + (128 * kslc) * 16, h2r + (128 * kslc - 512) * 64, 128, boff, acc);
        }
        reduce_acc(acc, sRed, kslc, half, lane);
        if (kslc == 0) cell_update(acc, cc2, g_h2[wb2], j0, jj, boff);
        __syncthreads();   // protect sRed before next phase A stores
    }

    grid_barrier();
    // final head: h2(T-1) is in buffer ((T-1)&1)^1 == 0
    do_y(TSTEPS - 1, g_h2[0], c, tid, sWO, sBO, sRY, out);
}

extern "C" void kernel_launch(void* const* d_in, const int* in_sizes, int n_in,
                              void* d_out, int out_size) {
    const float* x    = (const float*)d_in[0];
    const float* Wih1 = (const float*)d_in[1];
    const float* Whh1 = (const float*)d_in[2];
    const float* bih1 = (const float*)d_in[3];
    const float* bhh1 = (const float*)d_in[4];
    const float* Wih2 = (const float*)d_in[5];
    const float* Whh2 = (const float*)d_in[6];
    const float* bih2 = (const float*)d_in[7];
    const float* bhh2 = (const float*)d_in[8];
    const float* Wout = (const float*)d_in[9];
    const float* bout = (const float*)d_in[10];
    float* out = (float*)d_out;

    cudaFuncSetAttribute(lstm_persistent_kernel,
                         cudaFuncAttributeMaxDynamicSharedMemorySize, SMEM_BYTES);
    lstm_persistent_kernel<<<NCTA, NTHR, SMEM_BYTES>>>(
        x, Wih1, Whh1, bih1, bhh1, Wih2, Whh2, bih2, bhh2, Wout, bout, out);
}

// round 8
// speedup vs baseline: 1.8467x; 1.8467x over previous
#include <cuda_runtime.h>
#include <math.h>

#define BATCH 64
#define TSTEPS 1024
#define IND 64
#define HD 512
#define OUTD 64
#define NCTA 128
#define NTHR 512

typedef unsigned long long ull;

// ---------------- persistent device state ----------------
__device__ __align__(16) float g_h1[2][HD * BATCH];        // [j][b], b contiguous
__device__ __align__(16) float g_h2[2][HD * BATCH];
__device__ __align__(16) float g_xT[TSTEPS * IND * BATCH]; // [t][k][b]
__device__ unsigned g_gen;
__device__ unsigned g_count;

// ---------------- grid-wide sense barrier (128 CTAs, 1/SM) ----------------
__device__ __forceinline__ void grid_barrier() {
    __syncthreads();
    if (threadIdx.x == 0) {
        __threadfence();
        volatile unsigned* vg = &g_gen;
        unsigned my = *vg;
        if (atomicAdd(&g_count, 1u) == NCTA - 1u) {
            g_count = 0u;
            __threadfence();
            *vg = my + 1u;
        } else {
            while (*vg == my) { }
        }
        __threadfence();
    }
    __syncthreads();
}

__device__ __forceinline__ float sigf(float x) { return 1.0f / (1.0f + __expf(-x)); }

// ---------------- packed f32x2 helpers ----------------
__device__ __forceinline__ ull splat2(float v) {
    ull r; asm("mov.b64 %0, {%1, %1};" : "=l"(r) : "f"(v)); return r;
}
__device__ __forceinline__ ull pack2(float lo, float hi) {
    ull r; asm("mov.b64 %0, {%1, %2};" : "=l"(r) : "f"(lo), "f"(hi)); return r;
}
__device__ __forceinline__ void ffma2(ull& d, ull a, ull b) {
    asm("fma.rn.f32x2 %0, %1, %2, %0;" : "+l"(d) : "l"(a), "l"(b));
}
__device__ __forceinline__ ull addf2(ull a, ull b) {
    ull r; asm("add.rn.f32x2 %0, %1, %2;" : "=l"(r) : "l"(a), "l"(b)); return r;
}
__device__ __forceinline__ void unpack2(ull v, float& lo, float& hi) {
    asm("mov.b64 {%0, %1}, %2;" : "=f"(lo), "=f"(hi) : "l"(v));
}

// ---------------- SMEM layout (byte offsets) ----------------
#define O_WA   0                 // 576 k * 16 ull (splatted [k][jj][type])
#define O_WB   73728             // 1024 k * 16 ull
#define O_RED  204800            // 8 rows * 128 ulonglong2 = 16384 B
#define O_BA   221184            // 16 ull
#define O_BB   221312
#define O_WO   221440            // 512 f
#define O_BO   223488
#define O_RY   223504            // 8*64 f
#define SMEM_BYTES 225552

// ---------------- MAC pipeline: blocks of 2 k, double buffered ----------------
// One warp covers all 64 b, 4 jj. Lane: bgrp=lane>>2 (8 b), jj=lane&3.
__device__ __forceinline__ void ld2(ulonglong2 (&hb)[4], const float* __restrict__ hsrc,
                                    int k, int boff) {
    const ulonglong2* p0 = (const ulonglong2*)(hsrc + k * 64 + boff);
    const ulonglong2* p1 = (const ulonglong2*)(hsrc + (k + 1) * 64 + boff);
    hb[0] = __ldcg(p0); hb[1] = __ldcg(p0 + 1);
    hb[2] = __ldcg(p1); hb[3] = __ldcg(p1 + 1);
}
__device__ __forceinline__ void mm2(const ull* __restrict__ wp, const ulonglong2 (&hb)[4],
                                    ull (&acc)[4][4]) {
#pragma unroll
    for (int i = 0; i < 2; ++i) {
        const ulonglong2* w = (const ulonglong2*)(wp + i * 16);
        ulonglong2 wif = w[0], wgo = w[1];
        ulonglong2 hA = hb[2 * i], hB = hb[2 * i + 1];
        ffma2(acc[0][0], wif.x, hA.x); ffma2(acc[0][1], wif.y, hA.x);
        ffma2(acc[0][2], wgo.x, hA.x); ffma2(acc[0][3], wgo.y, hA.x);
        ffma2(acc[1][0], wif.x, hA.y); ffma2(acc[1][1], wif.y, hA.y);
        ffma2(acc[1][2], wgo.x, hA.y); ffma2(acc[1][3], wgo.y, hA.y);
        ffma2(acc[2][0], wif.x, hB.x); ffma2(acc[2][1], wif.y, hB.x);
        ffma2(acc[2][2], wgo.x, hB.x); ffma2(acc[2][3], wgo.y, hB.x);
        ffma2(acc[3][0], wif.x, hB.y); ffma2(acc[3][1], wif.y, hB.y);
        ffma2(acc[3][2], wgo.x, hB.y); ffma2(acc[3][3], wgo.y, hB.y);
    }
}
// n must be a multiple of 4 (36, 28, 8, 64 all are)
__device__ __forceinline__ void mac_run(const ull* __restrict__ wbase,
                                        const float* __restrict__ hsrc,
                                        int n, int boff, ull (&acc)[4][4]) {
    ulonglong2 hA[4], hB[4];
    ld2(hA, hsrc, 0, boff);
#pragma unroll 4
    for (int k = 0; k + 4 <= n; k += 4) {
        ld2(hB, hsrc, k + 2, boff);
        mm2(wbase + k * 16, hA, acc);
        if (k + 4 < n) ld2(hA, hsrc, k + 4, boff);
        mm2(wbase + (k + 2) * 16, hB, acc);
    }
}

// ---------------- 16-slice tree reduction (16 KB buffer, 7 syncs) ------------
__device__ __forceinline__ void red_store(ulonglong2* sRed, int slot, const ull (&acc)[4][4]) {
#pragma unroll
    for (int i = 0; i < 4; ++i) {
        sRed[(i * 2) * 128 + slot]     = make_ulonglong2(acc[i][0], acc[i][1]);
        sRed[(i * 2 + 1) * 128 + slot] = make_ulonglong2(acc[i][2], acc[i][3]);
    }
}
__device__ __forceinline__ void red_add(const ulonglong2* sRed, int slot, ull (&acc)[4][4]) {
#pragma unroll
    for (int i = 0; i < 4; ++i) {
        ulonglong2 a = sRed[(i * 2) * 128 + slot];
        ulonglong2 b = sRed[(i * 2 + 1) * 128 + slot];
        acc[i][0] = addf2(acc[i][0], a.x); acc[i][1] = addf2(acc[i][1], a.y);
        acc[i][2] = addf2(acc[i][2], b.x); acc[i][3] = addf2(acc[i][3], b.y);
    }
}
__device__ __forceinline__ void reduce16(ull (&acc)[4][4], ulonglong2* sRed,
                                         int warp, int lane) {
    // 16 -> 8 in two passes (buffer holds 4 warps' worth = 128 slots)
    if (warp >= 8 && warp < 12) red_store(sRed, (warp - 8) * 32 + lane, acc);
    __syncthreads();
    if (warp < 4) red_add(sRed, warp * 32 + lane, acc);
    __syncthreads();
    if (warp >= 12) red_store(sRed, (warp - 12) * 32 + lane, acc);
    __syncthreads();
    if (warp >= 4 && warp < 8) red_add(sRed, (warp - 4) * 32 + lane, acc);
    __syncthreads();
    // 8 -> 1 (3 rounds)
    if (warp >= 4 && warp < 8) red_store(sRed, (warp - 4) * 32 + lane, acc);
    __syncthreads();
    if (warp < 4) red_add(sRed, warp * 32 + lane, acc);
    __syncthreads();
    if (warp >= 1 && warp < 4) red_store(sRed, (warp - 1) * 32 + lane, acc);
    __syncthreads();
    if (warp == 0) {
#pragma unroll
        for (int w = 0; w < 3; ++w) red_add(sRed, w * 32 + lane, acc);
    }
}

// ---------------- activations + cell + h store (warp 0 only) ----------------
__device__ __forceinline__ void cell_update(ull (&acc)[4][4], ull (&cc)[4],
                                            float* __restrict__ hdst,
                                            int j0, int jj, int boff) {
    ull hout[4];
#pragma unroll
    for (int bp = 0; bp < 4; ++bp) {
        float gi0, gi1, gf0, gf1, gg0, gg1, go0, go1, c0, c1;
        unpack2(acc[bp][0], gi0, gi1);
        unpack2(acc[bp][1], gf0, gf1);
        unpack2(acc[bp][2], gg0, gg1);
        unpack2(acc[bp][3], go0, go1);
        unpack2(cc[bp], c0, c1);
        c0 = sigf(gf0) * c0 + sigf(gi0) * tanhf(gg0);
        c1 = sigf(gf1) * c1 + sigf(gi1) * tanhf(gg1);
        cc[bp] = pack2(c0, c1);
        hout[bp] = pack2(sigf(go0) * tanhf(c0), sigf(go1) * tanhf(c1));
    }
    ulonglong2* hd = (ulonglong2*)(hdst + (j0 + jj) * 64 + boff);
    hd[0] = make_ulonglong2(hout[0], hout[1]);
    hd[1] = make_ulonglong2(hout[2], hout[3]);
}

// ---------------- y(t) head: CTA c (<64) -> column c; 8-way k split ----------
__device__ __forceinline__ void do_y(int t, const float* __restrict__ h2v,
                                     int c, int tid,
                                     const float* sWO, const float* sBO,
                                     float* sRY, float* __restrict__ out) {
    int b = tid & 63, u = tid >> 6;   // u in 0..7
    if (c < OUTD) {
        float p = 0.0f;
        int k0 = u * 64;
#pragma unroll 8
        for (int k = 0; k < 64; ++k)
            p += __ldcg(h2v + (k0 + k) * 64 + b) * sWO[k0 + k];
        sRY[u * 64 + b] = p;
    }
    __syncthreads();
    if (c < OUTD && u == 0) {
        float y = sBO[0];
#pragma unroll
        for (int m = 0; m < 8; ++m) y += sRY[m * 64 + b];
        out[b * (TSTEPS * OUTD) + t * OUTD + c] = y;
    }
}

extern __shared__ char smem[];

__global__ void __launch_bounds__(NTHR, 1)
lstm_persistent_kernel(const float* __restrict__ x,
                       const float* __restrict__ Wih1, const float* __restrict__ Whh1,
                       const float* __restrict__ bih1, const float* __restrict__ bhh1,
                       const float* __restrict__ Wih2, const float* __restrict__ Whh2,
                       const float* __restrict__ bih2, const float* __restrict__ bhh2,
                       const float* __restrict__ Wout, const float* __restrict__ bout,
                       float* __restrict__ out) {
    ull* sWA = (ull*)(smem + O_WA);
    ull* sWB = (ull*)(smem + O_WB);
    ulonglong2* sRed = (ulonglong2*)(smem + O_RED);
    ull* sBA = (ull*)(smem + O_BA);
    ull* sBB = (ull*)(smem + O_BB);
    float* sWO = (float*)(smem + O_WO);
    float* sBO = (float*)(smem + O_BO);
    float* sRY = (float*)(smem + O_RY);

    const int tid  = threadIdx.x;
    const int c    = blockIdx.x;          // CTA owns j = c*4 .. c*4+3
    const int j0   = c * 4;
    const int warp = tid >> 5;            // = k-slice (0..15)
    const int lane = tid & 31;
    const int jj   = lane & 3;
    const int bgrp = lane >> 2;           // 0..7
    const int boff = bgrp * 8;            // float offset in 64-wide b row (8 b)

    // ---- stage splatted weights into SMEM (once) ----
    for (int i = tid; i < 576 * 16; i += NTHR) {
        int k = i >> 4, r = i & 15, jw = r >> 2, tp = r & 3;
        int row = tp * HD + j0 + jw;
        float v = (k < IND) ? Wih1[row * IND + k] : Whh1[row * HD + (k - IND)];
        sWA[i] = splat2(v);
    }
    for (int i = tid; i < 1024 * 16; i += NTHR) {
        int k = i >> 4, r = i & 15, jw = r >> 2, tp = r & 3;
        int row = tp * HD + j0 + jw;
        float v = (k < HD) ? Wih2[row * HD + k] : Whh2[row * HD + (k - HD)];
        sWB[i] = splat2(v);
    }
    if (tid < 16) {
        int jw = tid >> 2, tp = tid & 3;
        int row = tp * HD + j0 + jw;
        sBA[jw * 4 + tp] = splat2(bih1[row] + bhh1[row]);
        sBB[jw * 4 + tp] = splat2(bih2[row] + bhh2[row]);
    }
    if (c < OUTD) {
        for (int i = tid; i < HD; i += NTHR) sWO[i] = Wout[c * HD + i];
        if (tid == 0) sBO[0] = bout[c];
    }

    // ---- prologue: x -> [t][k][b]; zero h buffers ----
    for (int t = c * (TSTEPS / NCTA); t < (c + 1) * (TSTEPS / NCTA); ++t) {
        for (int i = tid; i < BATCH * IND; i += NTHR) {
            int b = i & 63, k = i >> 6;
            g_xT[t * (IND * BATCH) + k * 64 + b] = x[b * (TSTEPS * IND) + t * IND + k];
        }
    }
    if (c < 64) {
        int gi = c * NTHR + tid;
        g_h1[0][gi] = 0.0f; g_h1[1][gi] = 0.0f;
        g_h2[0][gi] = 0.0f; g_h2[1][gi] = 0.0f;
    }
    grid_barrier();

    ull cc1[4] = {0, 0, 0, 0}, cc2[4] = {0, 0, 0, 0};
    const ull* wA = sWA + jj * 4;
    const ull* wB = sWB + jj * 4;

    for (int t = 0; t < TSTEPS; ++t) {
        const int rp = t & 1, wb2 = rp ^ 1;
        const float* h1r = g_h1[rp];
        const float* h2r = g_h2[rp];
        const float* h1w = g_h1[wb2];

        // ======== phase A: gates1 = x_t W_ih1^T + h1 W_hh1^T + b ========
        ull acc[4][4];
#pragma unroll
        for (int i = 0; i < 4; ++i)
#pragma unroll
            for (int p = 0; p < 4; ++p)
                acc[i][p] = (warp == 0) ? sBA[jj * 4 + p] : 0ull;

        // 16-way k split over concat [x(64) | h1(512)], 36 k per slice
        if (warp == 0) {
            mac_run(wA, g_xT + t * (IND * BATCH), 36, boff, acc);
        } else if (warp == 1) {
            mac_run(wA + 36 * 16, g_xT + t * (IND * BATCH) + 36 * 64, 28, boff, acc);
            mac_run(wA + 64 * 16, h1r, 8, boff, acc);
        } else {
            mac_run(wA + (36 * warp) * 16, h1r + (36 * warp - 64) * 64, 36, boff, acc);
        }
        reduce16(acc, sRed, warp, lane);
        if (warp == 0) cell_update(acc, cc1, g_h1[wb2], j0, jj, boff);

        grid_barrier();   // publish h1(t); the ONLY grid barrier per step

        // deferred y(t-1) from h2(t-1)
        if (t > 0) do_y(t - 1, h2r, c, tid, sWO, sBO, sRY, out);

        // ======== phase B: gates2 = h1(t) W_ih2^T + h2(t-1) W_hh2^T + b ========
#pragma unroll
        for (int i = 0; i < 4; ++i)
#pragma unroll
            for (int p = 0; p < 4; ++p)
                acc[i][p] = (warp == 0) ? sBB[jj * 4 + p] : 0ull;

        // 16-way k split over concat [h1(512) | h2(512)], 64 k per slice
        if (warp < 8) {
            mac_run(wB + (64 * warp) * 16, h1w + (64 * warp) * 64, 64, boff, acc);
        } else {
            mac_run(wB + (64 * warp) * 16, h2r + (64 * warp - 512) * 64, 64, boff, acc);
        }
        reduce16(acc, sRed, warp, lane);
        if (warp == 0) cell_update(acc, cc2, g_h2[wb2], j0, jj, boff);
        __syncthreads();   // protect sRed before next step's phase-A stores
    }

    grid_barrier();
    // final head: h2(T-1) is in buffer ((T-1)&1)^1 == 0
    do_y(TSTEPS - 1, g_h2[0], c, tid, sWO, sBO, sRY, out);
}

extern "C" void kernel_launch(void* const* d_in, const int* in_sizes, int n_in,
                              void* d_out, int out_size) {
    const float* x    = (const float*)d_in[0];
    const float* Wih1 = (const float*)d_in[1];
    const float* Whh1 = (const float*)d_in[2];
    const float* bih1 = (const float*)d_in[3];
    const float* bhh1 = (const float*)d_in[4];
    const float* Wih2 = (const float*)d_in[5];
    const float* Whh2 = (const float*)d_in[6];
    const float* bih2 = (const float*)d_in[7];
    const float* bhh2 = (const float*)d_in[8];
    const float* Wout = (const float*)d_in[9];
    const float* bout = (const float*)d_in[10];
    float* out = (float*)d_out;

    cudaFuncSetAttribute(lstm_persistent_kernel,
                         cudaFuncAttributeMaxDynamicSharedMemorySize, SMEM_BYTES);
    lstm_persistent_kernel<<<NCTA, NTHR, SMEM_BYTES>>>(
        x, Wih1, Whh1, bih1, bhh1, Wih2, Whh2, bih2, bhh2, Wout, bout, out);
}